// round 8
// baseline (speedup 1.0000x reference)
#include <cuda_runtime.h>
#include <cuda_bf16.h>
#include <cstdint>

#define NSTATE (1u << 23)

// bf16 hi/lo state ping-pong (2 buffers x 2^24 elements) + pre-swizzled U image.
__device__ __nv_bfloat16 g_shi[2][1u << 24];
__device__ __nv_bfloat16 g_slo[2][1u << 24];
__device__ __nv_bfloat16 g_ubf[262144];   // 4 gates x 4 matrices x 16384 bf16

#define SMEM_BYTES 196608u
#define SGN 0x80008000u

// gates 0-2: U tiles [0,131072) (4 x 32768), state A buffers 131072 + buf*32768 (4 x 8192)
#define AL_OFF 131072u
// gate 3: U-half tiles [0,65536) (4 x 16384), state B buffers 65536 + buf*65536 (4 x 16384)
#define BH_OFF 65536u

__device__ __forceinline__ uint32_t smem_u32(const void* p) {
    uint32_t a;
    asm("{ .reg .u64 t; cvta.to.shared.u64 t, %1; cvt.u32.u64 %0, t; }" : "=r"(a) : "l"(p));
    return a;
}

#define CPASYNC16(saddr, gptr)                                                  \
    asm volatile("cp.async.cg.shared.global [%0], [%1], 16;"                    \
        :: "r"(saddr), "l"(gptr) : "memory")

#define LDM4(r, addr)                                                           \
    asm volatile("ldmatrix.sync.aligned.m8n8.x4.shared.b16 {%0,%1,%2,%3}, [%4];"\
        : "=r"((r)[0]), "=r"((r)[1]), "=r"((r)[2]), "=r"((r)[3]) : "r"(addr))

#define LDM4T(r, addr)                                                          \
    asm volatile("ldmatrix.sync.aligned.m8n8.x4.trans.shared.b16 {%0,%1,%2,%3}, [%4];"\
        : "=r"((r)[0]), "=r"((r)[1]), "=r"((r)[2]), "=r"((r)[3]) : "r"(addr))

#define MMA(C, A, b0v, b1v)                                                     \
    asm volatile("mma.sync.aligned.m16n8k16.row.col.f32.bf16.bf16.f32 "         \
        "{%0,%1,%2,%3}, {%4,%5,%6,%7}, {%8,%9}, {%0,%1,%2,%3};"                 \
        : "+f"((C)[0]), "+f"((C)[1]), "+f"((C)[2]), "+f"((C)[3])                \
        : "r"((A)[0]), "r"((A)[1]), "r"((A)[2]), "r"((A)[3]), "r"(b0v), "r"(b1v))

// 12-MMA block (R6-proven): ch1 = A_r*B_r - A_i*B_i ; ch0 = A_i*B_r + A_r*B_i
#define MMA12(A0, J2)                                                           \
    MMA(acc1[A0], af[0], bf[0][J2], bf[0][(J2) + 2]);                           \
    MMA(acc1[A0], af[0], bf[1][J2], bf[1][(J2) + 2]);                           \
    MMA(acc1[A0], af[1], bf[0][J2], bf[0][(J2) + 2]);                           \
    MMA(acc1[A0], naf2,  bf[2][J2], bf[2][(J2) + 2]);                           \
    MMA(acc1[A0], naf2,  bf[3][J2], bf[3][(J2) + 2]);                           \
    MMA(acc1[A0], naf3,  bf[2][J2], bf[2][(J2) + 2]);                           \
    MMA(acc0[A0], af[2], bf[0][J2], bf[0][(J2) + 2]);                           \
    MMA(acc0[A0], af[2], bf[1][J2], bf[1][(J2) + 2]);                           \
    MMA(acc0[A0], af[3], bf[0][J2], bf[0][(J2) + 2]);                           \
    MMA(acc0[A0], af[0], bf[2][J2], bf[2][(J2) + 2]);                           \
    MMA(acc0[A0], af[0], bf[3][J2], bf[3][(J2) + 2]);                           \
    MMA(acc0[A0], af[1], bf[2][J2], bf[2][(J2) + 2]);

__device__ __forceinline__ void packpair(float x0, float x1, uint32_t& h, uint32_t& l) {
    __nv_bfloat16 h0 = __float2bfloat16(x0), h1 = __float2bfloat16(x1);
    __nv_bfloat16 l0 = __float2bfloat16(x0 - __bfloat162float(h0));
    __nv_bfloat16 l1 = __float2bfloat16(x1 - __bfloat162float(h1));
    h = (uint32_t)__bfloat16_as_ushort(h0) | ((uint32_t)__bfloat16_as_ushort(h1) << 16);
    l = (uint32_t)__bfloat16_as_ushort(l0) | ((uint32_t)__bfloat16_as_ushort(l1) << 16);
}

// ---------------------------------------------------------------------------
__global__ void prep_u(const float* __restrict__ U)
{
    const int i = blockIdx.x * 256 + threadIdx.x;   // 131072
    const int a = i & 127, k = (i >> 7) & 127, c = (i >> 14) & 1, g = i >> 15;
    const float x = U[i];
    const __nv_bfloat16 hi = __float2bfloat16(x);
    const __nv_bfloat16 lo = __float2bfloat16(x - __bfloat162float(hi));
    const int h = k * 128 + (((a >> 3) ^ (k & 7)) << 3) + (a & 7);
    g_ubf[g * 65536 + (c * 2 + 0) * 16384 + h] = hi;
    g_ubf[g * 65536 + (c * 2 + 1) * 16384 + h] = lo;
}

// Initial fp32 state -> bf16 hi/lo planes (buffer 0). Pure bandwidth.
__global__ void prep_state(const float* __restrict__ in)
{
    const int i = blockIdx.x * 256 + threadIdx.x;   // 0..2^22-1, 4 floats each
    const float4 v = ((const float4*)in)[i];
    uint32_t h0, l0, h1, l1;
    packpair(v.x, v.y, h0, l0);
    packpair(v.z, v.w, h1, l1);
    ((uint2*)g_shi[0])[i] = make_uint2(h0, h1);
    ((uint2*)g_slo[0])[i] = make_uint2(l0, l1);
}

// ---------------------------------------------------------------------------
// Gates 0-2: persistent, U resident; state tiles staged by pure cp.async.
// stage one 32-row item (4 mats x 8KB) into buffer dbuf.
__device__ __forceinline__ void stage_low(uint32_t sb, const __nv_bfloat16* shi,
                                          const __nv_bfloat16* slo, int item, uint32_t dbuf)
{
    const int t = threadIdx.x;
    const size_t base = (size_t)item * 4096;
    #pragma unroll
    for (int s = 0; s < 8; ++s) {
        const int slot = t + 256 * s;              // 0..2047
        const int c = slot & 15, r = (slot >> 4) & 31, mat = slot >> 9;
        const int plane = mat & 1, ch = mat >> 1;
        const __nv_bfloat16* src = (plane ? slo : shi) + (size_t)ch * NSTATE + base + r * 128 + c * 8;
        const uint32_t dst = sb + AL_OFF + dbuf * 32768u + (uint32_t)mat * 8192u
                           + (uint32_t)r * 256u + (uint32_t)((c ^ (r & 7)) * 16);
        CPASYNC16(dst, src);
    }
    asm volatile("cp.async.commit_group;" ::: "memory");
}

__global__ void __launch_bounds__(256, 1)
gate_lowbf(const __nv_bfloat16* __restrict__ shi, const __nv_bfloat16* __restrict__ slo,
           __nv_bfloat16* __restrict__ ohi, __nv_bfloat16* __restrict__ olo,
           const __nv_bfloat16* __restrict__ img)
{
    extern __shared__ char smem[];
    const uint32_t sb = smem_u32(smem);
    const int t = threadIdx.x, lane = t & 31, w = t >> 5;

    // stage U image once (128KB, pre-swizzled)
    {
        const uint4* src = (const uint4*)img;
        #pragma unroll
        for (int j = 0; j < 32; ++j) {
            const int idx = t + 256 * j;
            CPASYNC16(sb + (uint32_t)idx * 16u, src + idx);
        }
        asm volatile("cp.async.commit_group;" ::: "memory");
    }

    int item = blockIdx.x;
    stage_low(sb, shi, slo, item, 0);
    asm volatile("cp.async.wait_group 0;" ::: "memory");
    __syncthreads();

    const int mrow0 = (w & 1) * 16, ncol0 = (w >> 1) * 32;
    const int ar = mrow0 + (lane & 15), acl = lane >> 4, ar7 = ar & 7;
    const int br_off = lane & 15, bcl = lane >> 4;
    const int rg = lane >> 2, tg = lane & 3;

    uint32_t buf = 0;
    for (; item < 2048; item += 148) {
        const int next = item + 148;
        const bool hasnext = next < 2048;
        if (hasnext) stage_low(sb, shi, slo, next, buf ^ 1u);

        float acc0[4][4], acc1[4][4];
        #pragma unroll
        for (int j = 0; j < 4; ++j)
            #pragma unroll
            for (int q = 0; q < 4; ++q) { acc0[j][q] = 0.f; acc1[j][q] = 0.f; }

        const uint32_t abase = sb + AL_OFF + buf * 32768u + (uint32_t)ar * 256u;
        #pragma unroll 1
        for (int ks = 0; ks < 8; ++ks) {
            uint32_t af[4][4], naf2[4], naf3[4];
            const uint32_t aa = abase + (uint32_t)(((ks * 2 + acl) ^ ar7) << 4);
            LDM4(af[0], aa);
            LDM4(af[1], aa + 8192);
            LDM4(af[2], aa + 16384);
            LDM4(af[3], aa + 24576);
            #pragma unroll
            for (int q = 0; q < 4; ++q) { naf2[q] = af[2][q] ^ SGN; naf3[q] = af[3][q] ^ SGN; }

            #pragma unroll
            for (int g = 0; g < 2; ++g) {
                uint32_t bf[4][4];
                const int row = ncol0 + g * 16 + br_off;
                const uint32_t ba = sb + (uint32_t)row * 256u
                                  + (uint32_t)((((ks * 2 + bcl) ^ (row & 7))) << 4);
                LDM4(bf[0], ba);
                LDM4(bf[1], ba + 32768);
                LDM4(bf[2], ba + 65536);
                LDM4(bf[3], ba + 98304);
                MMA12(g * 2 + 0, 0)
                MMA12(g * 2 + 1, 1)
            }
        }

        // epilogue: store bf16 hi/lo planes directly
        {
            const size_t row0 = (size_t)item * 32 + mrow0 + rg;
            #pragma unroll
            for (int j = 0; j < 4; ++j) {
                const int n = ncol0 + j * 8 + tg * 2;
                uint32_t h, l;
                packpair(acc0[j][0], acc0[j][1], h, l);          // ch0, row0
                *(uint32_t*)(ohi + row0 * 128 + n) = h;
                *(uint32_t*)(olo + row0 * 128 + n) = l;
                packpair(acc0[j][2], acc0[j][3], h, l);          // ch0, row0+8
                *(uint32_t*)(ohi + (row0 + 8) * 128 + n) = h;
                *(uint32_t*)(olo + (row0 + 8) * 128 + n) = l;
                packpair(acc1[j][0], acc1[j][1], h, l);          // ch1, row0
                *(uint32_t*)(ohi + NSTATE + row0 * 128 + n) = h;
                *(uint32_t*)(olo + NSTATE + row0 * 128 + n) = l;
                packpair(acc1[j][2], acc1[j][3], h, l);          // ch1, row0+8
                *(uint32_t*)(ohi + NSTATE + (row0 + 8) * 128 + n) = h;
                *(uint32_t*)(olo + NSTATE + (row0 + 8) * 128 + n) = l;
            }
        }
        if (hasnext) asm volatile("cp.async.wait_group 0;" ::: "memory");
        __syncthreads();
        buf ^= 1u;
    }
}

// ---------------------------------------------------------------------------
// Gate 3: persistent; A = U k-half resident; B = state (128a x 64l) via cp.async.
__device__ __forceinline__ void stage_high(uint32_t sb, const __nv_bfloat16* shi,
                                           const __nv_bfloat16* slo, int widx, uint32_t dbuf)
{
    const int t = threadIdx.x;
    const int chunk = widx >> 1, lh = widx & 1;
    const size_t cb = (size_t)chunk * 16384;
    #pragma unroll
    for (int s = 0; s < 16; ++s) {
        const int slot = t + 256 * s;              // 0..4095
        const int c = slot & 7, a = (slot >> 3) & 127, mat = slot >> 10;
        const int plane = mat & 1, ch = mat >> 1;
        const __nv_bfloat16* src = (plane ? slo : shi) + (size_t)ch * NSTATE + cb
                                 + a * 128 + lh * 64 + c * 8;
        const uint32_t dst = sb + BH_OFF + dbuf * 65536u + (uint32_t)mat * 16384u
                           + (uint32_t)a * 128u + (uint32_t)((c ^ (a & 7)) * 16);
        CPASYNC16(dst, src);
    }
    asm volatile("cp.async.commit_group;" ::: "memory");
}

__global__ void __launch_bounds__(256, 1)
gate_highbf(const __nv_bfloat16* __restrict__ shi, const __nv_bfloat16* __restrict__ slo,
            float* __restrict__ out, const __nv_bfloat16* __restrict__ img)
{
    extern __shared__ char smem[];
    const uint32_t sb = smem_u32(smem);
    const int t = threadIdx.x, lane = t & 31, w = t >> 5;
    const int khalf = blockIdx.x & 1;
    const int pairid = blockIdx.x >> 1;   // 0..73

    // stage U k-half once (64KB, pre-swizzled; 64 rows per matrix)
    {
        const uint4* src = (const uint4*)img;
        #pragma unroll
        for (int j = 0; j < 16; ++j) {
            const int idx = t + 256 * j;              // 0..4095
            const int m = idx >> 10, within = idx & 1023;
            CPASYNC16(sb + (uint32_t)idx * 16u, src + m * 2048 + khalf * 1024 + within);
        }
        asm volatile("cp.async.commit_group;" ::: "memory");
    }

    int widx = pairid;                    // 1024 = 512 chunks x 2 l-halves
    stage_high(sb, shi, slo, widx, 0);
    asm volatile("cp.async.wait_group 0;" ::: "memory");
    __syncthreads();

    const int mrow0 = (w & 3) * 16, ncol0 = (w >> 2) * 32;
    const int ar = mrow0 + (lane & 15), acl = lane >> 4, ar7 = ar & 7;
    const int br_off = (lane & 7) + ((lane & 16) >> 1), bcl = (lane >> 3) & 1;
    const int rg = lane >> 2, tg = lane & 3;
    const uint32_t abase = sb + (uint32_t)ar * 256u;

    uint32_t buf = 0;
    for (; widx < 1024; widx += 74) {
        const int chunk = widx >> 1, lh = widx & 1;
        const size_t cb = (size_t)chunk * 16384;
        const int nwidx = widx + 74;
        const bool hasnext = nwidx < 1024;
        if (hasnext) stage_high(sb, shi, slo, nwidx, buf ^ 1u);

        float acc0[4][4], acc1[4][4];
        #pragma unroll
        for (int j = 0; j < 4; ++j)
            #pragma unroll
            for (int q = 0; q < 4; ++q) { acc0[j][q] = 0.f; acc1[j][q] = 0.f; }

        const uint32_t bbuf = sb + BH_OFF + buf * 65536u;
        #pragma unroll 1
        for (int ks = 0; ks < 8; ++ks) {
            uint32_t af[4][4], naf2[4], naf3[4];
            const uint32_t aa = abase + (uint32_t)(((ks * 2 + acl) ^ ar7) << 4);
            LDM4(af[0], aa);
            LDM4(af[1], aa + 16384);
            LDM4(af[2], aa + 32768);
            LDM4(af[3], aa + 49152);
            #pragma unroll
            for (int q = 0; q < 4; ++q) { naf2[q] = af[2][q] ^ SGN; naf3[q] = af[3][q] ^ SGN; }

            #pragma unroll
            for (int g = 0; g < 2; ++g) {
                uint32_t bf[4][4];
                const int row = ks * 16 + br_off;
                const int cidx = ((ncol0 + g * 16) >> 3) + bcl;
                const uint32_t ba = bbuf + (uint32_t)row * 128u
                                  + (uint32_t)((cidx ^ (row & 7)) << 4);
                LDM4T(bf[0], ba);
                LDM4T(bf[1], ba + 16384);
                LDM4T(bf[2], ba + 32768);
                LDM4T(bf[3], ba + 49152);
                MMA12(g * 2 + 0, 0)
                MMA12(g * 2 + 1, 1)
            }
        }

        {
            const size_t row0 = (size_t)khalf * 64 + mrow0 + rg;
            float* o0 = out + cb;
            float* o1 = out + NSTATE + cb;
            #pragma unroll
            for (int j = 0; j < 4; ++j) {
                const int n = lh * 64 + ncol0 + j * 8 + tg * 2;
                *(float2*)(o0 + row0 * 128 + n)       = make_float2(acc0[j][0], acc0[j][1]);
                *(float2*)(o0 + (row0 + 8) * 128 + n) = make_float2(acc0[j][2], acc0[j][3]);
                *(float2*)(o1 + row0 * 128 + n)       = make_float2(acc1[j][0], acc1[j][1]);
                *(float2*)(o1 + (row0 + 8) * 128 + n) = make_float2(acc1[j][2], acc1[j][3]);
            }
        }
        if (hasnext) asm volatile("cp.async.wait_group 0;" ::: "memory");
        __syncthreads();
        buf ^= 1u;
    }
}

// ---------------------------------------------------------------------------
extern "C" void kernel_launch(void* const* d_in, const int* in_sizes, int n_in,
                              void* d_out, int out_size)
{
    const float* state = (const float*)d_in[0];
    const float* U     = (const float*)d_in[1];
    if (n_in >= 2 && in_sizes[0] < in_sizes[1]) {
        const float* tmp = state; state = U; U = tmp;
    }
    float* out = (float*)d_out;

    __nv_bfloat16 *shi = nullptr, *slo = nullptr, *ubf = nullptr;
    cudaGetSymbolAddress((void**)&shi, g_shi);
    cudaGetSymbolAddress((void**)&slo, g_slo);
    cudaGetSymbolAddress((void**)&ubf, g_ubf);
    __nv_bfloat16* shi1 = shi + (1u << 24);
    __nv_bfloat16* slo1 = slo + (1u << 24);

    cudaFuncSetAttribute(gate_lowbf,  cudaFuncAttributeMaxDynamicSharedMemorySize, (int)SMEM_BYTES);
    cudaFuncSetAttribute(gate_highbf, cudaFuncAttributeMaxDynamicSharedMemorySize, (int)SMEM_BYTES);

    prep_u<<<512, 256>>>(U);
    prep_state<<<16384, 256>>>(state);
    gate_lowbf<<<148, 256, SMEM_BYTES>>>(shi,  slo,  shi1, slo1, ubf);            // gate 0
    gate_lowbf<<<148, 256, SMEM_BYTES>>>(shi1, slo1, shi,  slo,  ubf + 65536);    // gate 1
    gate_lowbf<<<148, 256, SMEM_BYTES>>>(shi,  slo,  shi1, slo1, ubf + 131072);   // gate 2
    gate_highbf<<<148, 256, SMEM_BYTES>>>(shi1, slo1, out, ubf + 196608);         // gate 3
}

// round 9
// speedup vs baseline: 1.0946x; 1.0946x over previous
#include <cuda_runtime.h>
#include <cuda_bf16.h>
#include <cstdint>

#define NSTATE (1u << 23)

__device__ float g_scratch[1u << 24];
__device__ __nv_bfloat16 g_ubf[262144];   // 4 gates x 4 matrices x 16384 bf16

#define SMEM_BYTES 196608u
#define SGN 0x80008000u

// gates 0-2: U tiles [0,131072) (4 x 32768), state A buffers 131072 + buf*32768 (4 x 8192)
#define AL_OFF 131072u
// gate 3: U-half tiles [0,65536) (4 x 16384), state B buffers 65536 + buf*65536 (4 x 16384)
#define BH_OFF 65536u

__device__ __forceinline__ uint32_t smem_u32(const void* p) {
    uint32_t a;
    asm("{ .reg .u64 t; cvta.to.shared.u64 t, %1; cvt.u32.u64 %0, t; }" : "=r"(a) : "l"(p));
    return a;
}

#define CPASYNC16(saddr, gptr)                                                  \
    asm volatile("cp.async.cg.shared.global [%0], [%1], 16;"                    \
        :: "r"(saddr), "l"(gptr) : "memory")

#define LDM4(r, addr)                                                           \
    asm volatile("ldmatrix.sync.aligned.m8n8.x4.shared.b16 {%0,%1,%2,%3}, [%4];"\
        : "=r"((r)[0]), "=r"((r)[1]), "=r"((r)[2]), "=r"((r)[3]) : "r"(addr))

#define LDM4T(r, addr)                                                          \
    asm volatile("ldmatrix.sync.aligned.m8n8.x4.trans.shared.b16 {%0,%1,%2,%3}, [%4];"\
        : "=r"((r)[0]), "=r"((r)[1]), "=r"((r)[2]), "=r"((r)[3]) : "r"(addr))

#define MMA(C, A, b0v, b1v)                                                     \
    asm volatile("mma.sync.aligned.m16n8k16.row.col.f32.bf16.bf16.f32 "         \
        "{%0,%1,%2,%3}, {%4,%5,%6,%7}, {%8,%9}, {%0,%1,%2,%3};"                 \
        : "+f"((C)[0]), "+f"((C)[1]), "+f"((C)[2]), "+f"((C)[3])                \
        : "r"((A)[0]), "r"((A)[1]), "r"((A)[2]), "r"((A)[3]), "r"(b0v), "r"(b1v))

// 12-MMA block: ch1 = A_r*B_r - A_i*B_i ; ch0 = A_i*B_r + A_r*B_i (hi*hi+hi*lo+lo*hi)
#define MMA12(A0, J2)                                                           \
    MMA(acc1[A0], af[0], bf[0][J2], bf[0][(J2) + 2]);                           \
    MMA(acc1[A0], af[0], bf[1][J2], bf[1][(J2) + 2]);                           \
    MMA(acc1[A0], af[1], bf[0][J2], bf[0][(J2) + 2]);                           \
    MMA(acc1[A0], naf2,  bf[2][J2], bf[2][(J2) + 2]);                           \
    MMA(acc1[A0], naf2,  bf[3][J2], bf[3][(J2) + 2]);                           \
    MMA(acc1[A0], naf3,  bf[2][J2], bf[2][(J2) + 2]);                           \
    MMA(acc0[A0], af[2], bf[0][J2], bf[0][(J2) + 2]);                           \
    MMA(acc0[A0], af[2], bf[1][J2], bf[1][(J2) + 2]);                           \
    MMA(acc0[A0], af[3], bf[0][J2], bf[0][(J2) + 2]);                           \
    MMA(acc0[A0], af[0], bf[2][J2], bf[2][(J2) + 2]);                           \
    MMA(acc0[A0], af[0], bf[3][J2], bf[3][(J2) + 2]);                           \
    MMA(acc0[A0], af[1], bf[2][J2], bf[2][(J2) + 2]);

// fp32 x8 -> bf16 hi (16B) + bf16 lo (16B)
__device__ __forceinline__ void cvt8(float4 x, float4 y, uint4* hi, uint4* lo) {
    float f[8] = {x.x, x.y, x.z, x.w, y.x, y.y, y.z, y.w};
    uint32_t h[8], l[8];
    #pragma unroll
    for (int i = 0; i < 8; ++i) {
        __nv_bfloat16 hb = __float2bfloat16(f[i]);
        h[i] = (uint32_t)__bfloat16_as_ushort(hb);
        l[i] = (uint32_t)__bfloat16_as_ushort(__float2bfloat16(f[i] - __bfloat162float(hb)));
    }
    *hi = make_uint4(h[0] | (h[1] << 16), h[2] | (h[3] << 16),
                     h[4] | (h[5] << 16), h[6] | (h[7] << 16));
    *lo = make_uint4(l[0] | (l[1] << 16), l[2] | (l[3] << 16),
                     l[4] | (l[5] << 16), l[6] | (l[7] << 16));
}

// ---------------------------------------------------------------------------
__global__ void prep_u(const float* __restrict__ U)
{
    const int i = blockIdx.x * 256 + threadIdx.x;   // 131072
    const int a = i & 127, k = (i >> 7) & 127, c = (i >> 14) & 1, g = i >> 15;
    const float x = U[i];
    const __nv_bfloat16 hi = __float2bfloat16(x);
    const __nv_bfloat16 lo = __float2bfloat16(x - __bfloat162float(hi));
    const int h = k * 128 + (((a >> 3) ^ (k & 7)) << 3) + (a & 7);
    g_ubf[g * 65536 + (c * 2 + 0) * 16384 + h] = hi;
    g_ubf[g * 65536 + (c * 2 + 1) * 16384 + h] = lo;
}

// ---------------------------------------------------------------------------
// Gates 0-2, persistent, 512 threads: U resident; 32-row chunks double-buffered.
// 16 warps: each owns a 16-row x 16-col output tile.
__global__ void __launch_bounds__(512, 1)
gate_lowp(const float* __restrict__ in, float* __restrict__ out,
          const __nv_bfloat16* __restrict__ img)
{
    extern __shared__ char smem[];
    const uint32_t sb = smem_u32(smem);
    const int t = threadIdx.x, lane = t & 31, w = t >> 5;

    // stage U image once (128KB, pre-swizzled)
    {
        const uint4* src = (const uint4*)img;
        #pragma unroll
        for (int j = 0; j < 16; ++j) {
            const int idx = t + 512 * j;
            CPASYNC16(sb + (uint32_t)idx * 16u, src + idx);
        }
        asm volatile("cp.async.commit_group;" ::: "memory");
    }

    int item = blockIdx.x;
    // first chunk convert (1024 slots, 2 per thread)
    {
        const size_t base = (size_t)item * 4096;
        #pragma unroll
        for (int s = 0; s < 2; ++s) {
            const int slot = t + 512 * s;
            const int c = slot & 15, r = (slot >> 4) & 31, ch = slot >> 9;
            const float4* p = (const float4*)(in + (size_t)ch * NSTATE + base + r * 128 + c * 8);
            uint4 hi, lo;
            cvt8(p[0], p[1], &hi, &lo);
            char* wp = smem + AL_OFF + (ch * 2) * 8192 + r * 256 + ((c ^ (r & 7)) * 16);
            *(uint4*)wp = hi;
            *(uint4*)(wp + 8192) = lo;
        }
    }
    asm volatile("cp.async.wait_group 0;" ::: "memory");
    __syncthreads();

    const int mrow0 = (w & 1) * 16, ncol0 = (w >> 1) * 16;
    const int ar = mrow0 + (lane & 15), acl = lane >> 4, ar7 = ar & 7;
    const int br_off = lane & 15, bcl = lane >> 4;
    const int rg = lane >> 2, tg = lane & 3;

    uint32_t buf = 0;
    for (; item < 2048; item += 148) {
        const int next = item + 148;
        const bool hasnext = next < 2048;
        float4 stg[4];
        if (hasnext) {
            const size_t base = (size_t)next * 4096;
            #pragma unroll
            for (int s = 0; s < 2; ++s) {
                const int slot = t + 512 * s;
                const int c = slot & 15, r = (slot >> 4) & 31, ch = slot >> 9;
                const float4* p = (const float4*)(in + (size_t)ch * NSTATE + base + r * 128 + c * 8);
                stg[2 * s] = p[0];
                stg[2 * s + 1] = p[1];
            }
        }

        float acc0[2][4], acc1[2][4];
        #pragma unroll
        for (int j = 0; j < 2; ++j)
            #pragma unroll
            for (int q = 0; q < 4; ++q) { acc0[j][q] = 0.f; acc1[j][q] = 0.f; }

        const uint32_t abase = sb + AL_OFF + buf * 32768u + (uint32_t)ar * 256u;
        const int brow = ncol0 + br_off;
        const uint32_t bbase = sb + (uint32_t)brow * 256u;
        const int br7 = brow & 7;
        #pragma unroll 1
        for (int ks = 0; ks < 8; ++ks) {
            uint32_t af[4][4], naf2[4], naf3[4];
            const uint32_t aa = abase + (uint32_t)(((ks * 2 + acl) ^ ar7) << 4);
            LDM4(af[0], aa);
            LDM4(af[1], aa + 8192);
            LDM4(af[2], aa + 16384);
            LDM4(af[3], aa + 24576);
            #pragma unroll
            for (int q = 0; q < 4; ++q) { naf2[q] = af[2][q] ^ SGN; naf3[q] = af[3][q] ^ SGN; }

            uint32_t bf[4][4];
            const uint32_t ba = bbase + (uint32_t)(((ks * 2 + bcl) ^ br7) << 4);
            LDM4(bf[0], ba);
            LDM4(bf[1], ba + 32768);
            LDM4(bf[2], ba + 65536);
            LDM4(bf[3], ba + 98304);
            MMA12(0, 0)
            MMA12(1, 1)
        }

        if (hasnext) {
            #pragma unroll
            for (int s = 0; s < 2; ++s) {
                const int slot = t + 512 * s;
                const int c = slot & 15, r = (slot >> 4) & 31, ch = slot >> 9;
                uint4 hi, lo;
                cvt8(stg[2 * s], stg[2 * s + 1], &hi, &lo);
                char* wp = smem + AL_OFF + (buf ^ 1u) * 32768u + (ch * 2) * 8192 + r * 256
                         + ((c ^ (r & 7)) * 16);
                *(uint4*)wp = hi;
                *(uint4*)(wp + 8192) = lo;
            }
        }

        {
            const size_t row0 = (size_t)item * 32 + mrow0 + rg;
            float* o0 = out;
            float* o1 = out + NSTATE;
            #pragma unroll
            for (int j = 0; j < 2; ++j) {
                const int n = ncol0 + j * 8 + tg * 2;
                *(float2*)(o0 + row0 * 128 + n)       = make_float2(acc0[j][0], acc0[j][1]);
                *(float2*)(o0 + (row0 + 8) * 128 + n) = make_float2(acc0[j][2], acc0[j][3]);
                *(float2*)(o1 + row0 * 128 + n)       = make_float2(acc1[j][0], acc1[j][1]);
                *(float2*)(o1 + (row0 + 8) * 128 + n) = make_float2(acc1[j][2], acc1[j][3]);
            }
        }
        __syncthreads();
        buf ^= 1u;
    }
}

// ---------------------------------------------------------------------------
// Gate 3, persistent, 512 threads: A = U k-half resident; B double-buffered.
// 16 warps: each owns a 16-row(k) x 16-col(l) output tile.
__global__ void __launch_bounds__(512, 1)
gate_highp(const float* __restrict__ in, float* __restrict__ out,
           const __nv_bfloat16* __restrict__ img)
{
    extern __shared__ char smem[];
    const uint32_t sb = smem_u32(smem);
    const int t = threadIdx.x, lane = t & 31, w = t >> 5;
    const int khalf = blockIdx.x & 1;
    const int pairid = blockIdx.x >> 1;   // 0..73

    // stage U k-half once (64KB, pre-swizzled; 64 rows per matrix)
    {
        const uint4* src = (const uint4*)img;
        #pragma unroll
        for (int j = 0; j < 8; ++j) {
            const int idx = t + 512 * j;              // 0..4095
            const int m = idx >> 10, within = idx & 1023;
            CPASYNC16(sb + (uint32_t)idx * 16u, src + m * 2048 + khalf * 1024 + within);
        }
        asm volatile("cp.async.commit_group;" ::: "memory");
    }

    int widx = pairid;                    // 1024 = 512 chunks x 2 l-halves
    // first item convert (2048 slots, 4 per thread)
    {
        const int chunk = widx >> 1, lh = widx & 1;
        const size_t cb = (size_t)chunk * 16384;
        #pragma unroll
        for (int s = 0; s < 4; ++s) {
            const int slot = t + 512 * s;
            const int c = slot & 7, a = (slot >> 3) & 127, ch = slot >> 10;
            const float4* p = (const float4*)(in + (size_t)ch * NSTATE + cb + a * 128 + lh * 64 + c * 8);
            uint4 hi, lo;
            cvt8(p[0], p[1], &hi, &lo);
            char* wp = smem + BH_OFF + (ch * 2) * 16384 + a * 128 + ((c ^ (a & 7)) * 16);
            *(uint4*)wp = hi;
            *(uint4*)(wp + 16384) = lo;
        }
    }
    asm volatile("cp.async.wait_group 0;" ::: "memory");
    __syncthreads();

    const int mrow0 = (w & 3) * 16, ncol0 = (w >> 2) * 16;
    const int ar = mrow0 + (lane & 15), acl = lane >> 4, ar7 = ar & 7;
    const int br_off = (lane & 7) + ((lane & 16) >> 1), bcl = (lane >> 3) & 1;
    const int rg = lane >> 2, tg = lane & 3;
    const uint32_t abase = sb + (uint32_t)ar * 256u;
    const int cidx = (ncol0 >> 3) + bcl;

    uint32_t buf = 0;
    for (; widx < 1024; widx += 74) {
        const int chunk = widx >> 1, lh = widx & 1;
        const size_t cb = (size_t)chunk * 16384;
        const int nwidx = widx + 74;
        const bool hasnext = nwidx < 1024;
        const int nchunk = nwidx >> 1, nlh = nwidx & 1;
        const size_t ncb = (size_t)nchunk * 16384;

        float4 stg[4];                    // 2 slots staged; 2 loaded after MMA
        if (hasnext) {
            #pragma unroll
            for (int s = 0; s < 2; ++s) {
                const int slot = t + 512 * s;
                const int c = slot & 7, a = (slot >> 3) & 127, ch = slot >> 10;
                const float4* p = (const float4*)(in + (size_t)ch * NSTATE + ncb + a * 128 + nlh * 64 + c * 8);
                stg[2 * s] = p[0];
                stg[2 * s + 1] = p[1];
            }
        }

        float acc0[2][4], acc1[2][4];
        #pragma unroll
        for (int j = 0; j < 2; ++j)
            #pragma unroll
            for (int q = 0; q < 4; ++q) { acc0[j][q] = 0.f; acc1[j][q] = 0.f; }

        const uint32_t bbuf = sb + BH_OFF + buf * 65536u;
        #pragma unroll 1
        for (int ks = 0; ks < 8; ++ks) {
            uint32_t af[4][4], naf2[4], naf3[4];
            const uint32_t aa = abase + (uint32_t)(((ks * 2 + acl) ^ ar7) << 4);
            LDM4(af[0], aa);
            LDM4(af[1], aa + 16384);
            LDM4(af[2], aa + 32768);
            LDM4(af[3], aa + 49152);
            #pragma unroll
            for (int q = 0; q < 4; ++q) { naf2[q] = af[2][q] ^ SGN; naf3[q] = af[3][q] ^ SGN; }

            uint32_t bf[4][4];
            const int row = ks * 16 + br_off;
            const uint32_t ba = bbuf + (uint32_t)row * 128u
                              + (uint32_t)((cidx ^ (row & 7)) << 4);
            LDM4T(bf[0], ba);
            LDM4T(bf[1], ba + 16384);
            LDM4T(bf[2], ba + 32768);
            LDM4T(bf[3], ba + 49152);
            MMA12(0, 0)
            MMA12(1, 1)
        }

        if (hasnext) {
            #pragma unroll
            for (int s = 0; s < 2; ++s) {
                const int slot = t + 512 * s;
                const int c = slot & 7, a = (slot >> 3) & 127, ch = slot >> 10;
                uint4 hi, lo;
                cvt8(stg[2 * s], stg[2 * s + 1], &hi, &lo);
                char* wp = smem + BH_OFF + (buf ^ 1u) * 65536u + (ch * 2) * 16384 + a * 128
                         + ((c ^ (a & 7)) * 16);
                *(uint4*)wp = hi;
                *(uint4*)(wp + 16384) = lo;
            }
            #pragma unroll
            for (int s = 2; s < 4; ++s) {
                const int slot = t + 512 * s;
                const int c = slot & 7, a = (slot >> 3) & 127, ch = slot >> 10;
                const float4* p = (const float4*)(in + (size_t)ch * NSTATE + ncb + a * 128 + nlh * 64 + c * 8);
                uint4 hi, lo;
                cvt8(p[0], p[1], &hi, &lo);
                char* wp = smem + BH_OFF + (buf ^ 1u) * 65536u + (ch * 2) * 16384 + a * 128
                         + ((c ^ (a & 7)) * 16);
                *(uint4*)wp = hi;
                *(uint4*)(wp + 16384) = lo;
            }
        }

        {
            const size_t row0 = (size_t)khalf * 64 + mrow0 + rg;
            float* o0 = out + cb;
            float* o1 = out + NSTATE + cb;
            #pragma unroll
            for (int j = 0; j < 2; ++j) {
                const int n = lh * 64 + ncol0 + j * 8 + tg * 2;
                *(float2*)(o0 + row0 * 128 + n)       = make_float2(acc0[j][0], acc0[j][1]);
                *(float2*)(o0 + (row0 + 8) * 128 + n) = make_float2(acc0[j][2], acc0[j][3]);
                *(float2*)(o1 + row0 * 128 + n)       = make_float2(acc1[j][0], acc1[j][1]);
                *(float2*)(o1 + (row0 + 8) * 128 + n) = make_float2(acc1[j][2], acc1[j][3]);
            }
        }
        __syncthreads();
        buf ^= 1u;
    }
}

// ---------------------------------------------------------------------------
extern "C" void kernel_launch(void* const* d_in, const int* in_sizes, int n_in,
                              void* d_out, int out_size)
{
    const float* state = (const float*)d_in[0];
    const float* U     = (const float*)d_in[1];
    if (n_in >= 2 && in_sizes[0] < in_sizes[1]) {
        const float* tmp = state; state = U; U = tmp;
    }
    float* out = (float*)d_out;

    float* scratch = nullptr;
    cudaGetSymbolAddress((void**)&scratch, g_scratch);
    __nv_bfloat16* ubf = nullptr;
    cudaGetSymbolAddress((void**)&ubf, g_ubf);

    cudaFuncSetAttribute(gate_lowp,  cudaFuncAttributeMaxDynamicSharedMemorySize, (int)SMEM_BYTES);
    cudaFuncSetAttribute(gate_highp, cudaFuncAttributeMaxDynamicSharedMemorySize, (int)SMEM_BYTES);

    prep_u<<<512, 256>>>(U);
    gate_lowp<<<148, 512, SMEM_BYTES>>>(state,   scratch, ubf);            // gate 0
    gate_lowp<<<148, 512, SMEM_BYTES>>>(scratch, out,     ubf + 65536);    // gate 1
    gate_lowp<<<148, 512, SMEM_BYTES>>>(out,     scratch, ubf + 131072);   // gate 2
    gate_highp<<<148, 512, SMEM_BYTES>>>(scratch, out,    ubf + 196608);   // gate 3
}